// round 8
// baseline (speedup 1.0000x reference)
#include <cuda_runtime.h>
#include <cuda_bf16.h>
#include <math.h>
#include <stdint.h>

constexpr int V_ = 4;
constexpr int NK = 6;
constexpr int PP = 7;
constexpr int NPCH = 9;            // nodes per half
constexpr int NPC = 18;            // nodes per CTA
constexpr int NT = 512;

// unified 8KB weight chunks [64 n_local][64 kl], bf16, swizzled.
constexpr int CHK = 8192;
constexpr int L1OFF  = 0;          // 8  chunks (4 per wg)
constexpr int CTXOFF = 8  * CHK;   // 24 chunks (12 per wg)
constexpr int L2OFF  = 32 * CHK;   // 32 chunks (16 per wg)
constexpr int L3OFF  = 64 * CHK;   // 32
constexpr int L4OFF  = 96 * CHK;   // 16 chunks (8 per wg)
constexpr int VSTRIDE = 112 * CHK; // 917504

__device__ uint8_t g_wB[(size_t)V_ * VSTRIDE];
__device__ float   g_cst3[V_][256];

// ---- per-half smem offsets ----
constexpr int OFF_W    = 0;        // 2 wg x 2 x 8KB = 32768
constexpr int OFF_AHI  = 32768;    // 68 slots x 512B = 34816 (64 layer + 4 vol)
constexpr int OFF_ALO  = 67584;    // 34816
constexpr int OFF_CTXP = 102400;   // 9*260*4 = 9360 (svol temp during preamble)
constexpr int OFF_ARP  = 111808;   // 512
constexpr int OFF_ARW  = 112320;   // 256
constexpr int OFF_INVD = 112576;   // 288
constexpr int OFF_DSUM = 112864;   // 48
constexpr int HALF_BYTES = 113152;
constexpr int SMEM_BYTES = 2 * HALF_BYTES;   // 226304

// ============================ PTX helpers ====================================
__device__ __forceinline__ uint32_t su32(const void* p) {
    return (uint32_t)__cvta_generic_to_shared(p);
}
__device__ __forceinline__ void cp16(uint8_t* s, const uint8_t* g) {
    uint32_t sa = su32(s);
    asm volatile("cp.async.cg.shared.global [%0], [%1], 16;" :: "r"(sa), "l"(g));
}
#define CP_COMMIT() asm volatile("cp.async.commit_group;" ::: "memory")
#define CP_WAIT1()  asm volatile("cp.async.wait_group 1;" ::: "memory")
#define CP_WAIT0()  asm volatile("cp.async.wait_group 0;" ::: "memory")
#define BARN(id, n) asm volatile("bar.sync %0, %1;" :: "r"(id), "r"(n) : "memory")

#define MMA_BF16(acc, a, b0, b1) asm volatile( \
    "mma.sync.aligned.m16n8k16.row.col.f32.bf16.bf16.f32 " \
    "{%0,%1,%2,%3}, {%4,%5,%6,%7}, {%8,%9}, {%0,%1,%2,%3};" \
    : "+f"((acc)[0]), "+f"((acc)[1]), "+f"((acc)[2]), "+f"((acc)[3]) \
    : "r"((a).x), "r"((a).y), "r"((a).z), "r"((a).w), "r"(b0), "r"(b1))

#define LDSM4(r0, r1, r2, r3, addr) asm volatile( \
    "ldmatrix.sync.aligned.m8n8.x4.shared.b16 {%0,%1,%2,%3}, [%4];" \
    : "=r"(r0), "=r"(r1), "=r"(r2), "=r"(r3) : "r"(addr))

__device__ __forceinline__ void relu_split(float x, float y, uint32_t& h, uint32_t& l) {
    x = fmaxf(x, 0.f); y = fmaxf(y, 0.f);
    __nv_bfloat162 hb = __float22bfloat162_rn(make_float2(x, y));
    float2 hf = __bfloat1622float2(hb);
    __nv_bfloat162 lb = __float22bfloat162_rn(make_float2(x - hf.x, y - hf.y));
    h = *reinterpret_cast<uint32_t*>(&hb);
    l = *reinterpret_cast<uint32_t*>(&lb);
}
__device__ __forceinline__ void plain_split(float x, float y, uint32_t& h, uint32_t& l) {
    __nv_bfloat162 hb = __float22bfloat162_rn(make_float2(x, y));
    float2 hf = __bfloat1622float2(hb);
    __nv_bfloat162 lb = __float22bfloat162_rn(make_float2(x - hf.x, y - hf.y));
    h = *reinterpret_cast<uint32_t*>(&hb);
    l = *reinterpret_cast<uint32_t*>(&lb);
}

// ===================== side kernel 1: cst3 ===================================
__global__ void cst3_kernel(const float* __restrict__ gpv, const float* __restrict__ gpr,
                            const float* __restrict__ pW, const float* __restrict__ pb,
                            const float* __restrict__ aW1, const float* __restrict__ ab1)
{
    __shared__ float pe[32];
    const int t = threadIdx.x;
    const float p0 = gpv[0] / gpr[0], p1 = gpv[1] / gpr[1];
    if (t < 32) pe[t] = fmaxf(pb[t] + p0 * pW[t] + p1 * pW[32 + t], 0.f);
    __syncthreads();
    for (int idx = t; idx < V_ * 256; idx += blockDim.x) {
        const int v = idx >> 8, c = idx & 255;
        const float* W = aW1 + ((size_t)v * 448 + 416) * 256 + c;
        float s = ab1[v * 256 + c];
#pragma unroll
        for (int k = 0; k < 32; k++) s += pe[k] * W[(size_t)k * 256];
        g_cst3[v][c] = s;
    }
}

// ===================== side kernel 2: weight convert =========================
__global__ void wconv_kernel(const float* __restrict__ bW1,
                             const float* __restrict__ bW2,
                             const float* __restrict__ aW1,
                             const float* __restrict__ aW2)
{
    const int total = V_ * 112 * 4096;
    for (int idx = blockIdx.x * blockDim.x + threadIdx.x; idx < total;
         idx += gridDim.x * blockDim.x) {
        const int v = idx / (112 * 4096);
        const int e = idx % (112 * 4096);
        const int c = e >> 12;
        const int r = e & 4095;
        const int n_local = r >> 6, kl = r & 63;
        float wv = 0.f;
        bool hi;
        if (c < 8) {                               // L1 (K padded 7->64)
            const int wg = c >> 2, cc = c & 3;
            hi = (cc >> 1) == 0;
            const int nh = cc & 1;
            const int n = wg * 128 + nh * 64 + n_local;
            if (kl < 7) wv = bW1[((size_t)v * 7 + kl) * 256 + n];
        } else if (c < 32) {                       // CTX (K padded 160->192)
            const int c2 = c - 8;
            const int wg = c2 / 12, cc = c2 % 12;
            hi = (cc / 6) == 0;
            const int r6 = cc % 6, kk = r6 >> 1, nh = r6 & 1;
            const int n = wg * 128 + nh * 64 + n_local;
            const int k = kk * 64 + kl;
            if (k < 160) wv = aW1[((size_t)v * 448 + 256 + k) * 256 + n];
        } else if (c < 64) {                       // L2
            const int c2 = c - 32;
            const int wg = c2 >> 4, cc = c2 & 15;
            hi = (cc >> 3) == 0;
            const int kk = (cc & 7) >> 1, nh = cc & 1;
            const int n = wg * 128 + nh * 64 + n_local;
            const int k = kk * 64 + kl;
            wv = bW2[((size_t)v * 256 + k) * 256 + n];
        } else if (c < 96) {                       // L3
            const int c2 = c - 64;
            const int wg = c2 >> 4, cc = c2 & 15;
            hi = (cc >> 3) == 0;
            const int kk = (cc & 7) >> 1, nh = cc & 1;
            const int n = wg * 128 + nh * 64 + n_local;
            const int k = kk * 64 + kl;
            wv = aW1[((size_t)v * 448 + k) * 256 + n];
        } else {                                   // L4 (N=128)
            const int c2 = c - 96;
            const int wg = c2 >> 3, cc = c2 & 7;
            hi = (cc >> 2) == 0;
            const int kk = cc & 3;
            const int n = wg * 64 + n_local;
            const int k = kk * 64 + kl;
            wv = aW2[((size_t)v * 256 + k) * 128 + n];
        }
        __nv_bfloat16 h = __float2bfloat16_rn(wv);
        __nv_bfloat16 val = hi ? h : __float2bfloat16_rn(wv - __bfloat162float(h));
        uint8_t* p = g_wB + (size_t)v * VSTRIDE + (size_t)c * CHK
                   + n_local * 128 + (((uint32_t)(kl * 2)) ^ (((uint32_t)n_local & 7) << 4));
        *reinterpret_cast<__nv_bfloat16*>(p) = val;
    }
}

// ===================== per-wg copy / prefetch ================================
__device__ __forceinline__ void copy_chunk(uint8_t* dst, const uint8_t* src, int tw) {
#pragma unroll
    for (int i = 0; i < 4; i++)
        cp16(dst + (tw + i * 128) * 16, src + (size_t)(tw + i * 128) * 16);
}
__device__ __forceinline__ void prefetchW(uint8_t* sbW, const uint8_t* wsrc, int tw) {
    copy_chunk(sbW, wsrc, tw);        CP_COMMIT();
    copy_chunk(sbW + CHK, wsrc + CHK, tw); CP_COMMIT();
}

// ===================== generic mainloop ======================================
// MODE: 0=CTX(12 chunks), 1=L1(4), 2=BIG(16), 3=L4(8)
template <int MODE>
__device__ __forceinline__ void run_ml(
    uint8_t* sbW, const uint8_t* wsrc, int tw, int barw,
    const uint4* AHI, const uint4* ALO, int lane, int wm, float (*acc)[4])
{
    constexpr int NCHUNK = (MODE == 0) ? 12 : (MODE == 1) ? 4 : (MODE == 2) ? 16 : 8;
    constexpr int SCNT   = (MODE == 1) ? 1 : 4;
    const uint32_t swzc = ((uint32_t)lane & 7) << 4;
    const int nbase = 8 * ((lane >> 4) & 1) + (lane & 7);
    const int kadd = ((lane >> 3) & 1) * 8;
#pragma unroll 1
    for (int c = 0; c < NCHUNK; c++) {
        if (c < NCHUNK - 1) CP_WAIT1(); else CP_WAIT0();
        BARN(barw, 128);
        const uint32_t wb = su32(sbW + (c & 1) * CHK);
        const bool hiB = (c < NCHUNK / 2);
        int aslot0, accB, nlb, jjn;
        bool active = true;
        if constexpr (MODE == 0) {
            const int r6 = c % 6, kk = r6 >> 1, nh = r6 & 1;
            active = (nh == (wm >> 1));
            nlb = (wm & 1) * 32; aslot0 = kk * 4; accB = 0; jjn = 2;
        } else if constexpr (MODE == 1) {
            nlb = 0; aslot0 = 64 + wm; accB = (c & 1) * 8; jjn = 4;
        } else if constexpr (MODE == 2) {
            const int kk = (c & 7) >> 1;
            nlb = 0; aslot0 = wm * 16 + kk * 4; accB = (c & 1) * 8; jjn = 4;
        } else {
            const int kk = c & 3;
            nlb = 0; aslot0 = wm * 16 + kk * 4; accB = 0; jjn = 4;
        }
        if (active) {
#pragma unroll
            for (int s = 0; s < SCNT; s++) {
                const uint4 ah = AHI[(aslot0 + s) * 32 + lane];
                uint4 al = make_uint4(0, 0, 0, 0);
                if (hiB) al = ALO[(aslot0 + s) * 32 + lane];
                const int koff = s * 16 + kadd;
                const uint32_t ba = wb + (uint32_t)((nlb + nbase) * 128)
                                  + (((uint32_t)(koff * 2)) ^ swzc);
#pragma unroll
                for (int jj = 0; jj < jjn; jj++) {
                    uint32_t b0, b1, b2, b3;
                    LDSM4(b0, b1, b2, b3, ba + jj * 2048);
                    MMA_BF16(acc[accB + 2 * jj],     ah, b0, b1);
                    MMA_BF16(acc[accB + 2 * jj + 1], ah, b2, b3);
                    if (hiB) {
                        MMA_BF16(acc[accB + 2 * jj],     al, b0, b1);
                        MMA_BF16(acc[accB + 2 * jj + 1], al, b2, b3);
                    }
                }
            }
        }
        BARN(barw, 128);
        if (c + 2 < NCHUNK) {
            copy_chunk(sbW + (c & 1) * CHK, wsrc + (size_t)(c + 2) * CHK, tw);
            CP_COMMIT();
        }
    }
}

// ===================== epilogue: C frags -> A frags =========================
// MODE 0: gmem bias (addv = fp32 bias base); MODE 1: per-node ctxp (smem).
template <int MODE>
__device__ __forceinline__ void epiA(
    uint8_t* sbH, float (*acc)[4], const float* __restrict__ addv,
    int wm, int wg, int lane)
{
    uint4* AHI = (uint4*)(sbH + OFF_AHI);
    uint4* ALO = (uint4*)(sbH + OFF_ALO);
    const int quad = lane >> 2, q4 = lane & 3;
    const int r0 = 16 * wm + quad;
    int n0 = r0 / 7;       if (n0 > 8) n0 = 8;
    int n1 = (r0 + 8) / 7; if (n1 > 8) n1 = 8;
#pragma unroll
    for (int u = 0; u < 8; u++) {
        const int c0 = wg * 128 + 16 * u + 2 * q4;
        const int c2 = c0 + 8;
        float2 a00, a01, a10, a11;
        if constexpr (MODE == 0) {
            a00 = __ldg((const float2*)(addv + c0));
            a01 = __ldg((const float2*)(addv + c2));
            a10 = a00; a11 = a01;
        } else {
            a00 = *(const float2*)(addv + n0 * 260 + c0);
            a01 = *(const float2*)(addv + n0 * 260 + c2);
            a10 = *(const float2*)(addv + n1 * 260 + c0);
            a11 = *(const float2*)(addv + n1 * 260 + c2);
        }
        uint32_t h0, l0, h1, l1, h2, l2, h3, l3;
        relu_split(acc[2*u][0]   + a00.x, acc[2*u][1]   + a00.y, h0, l0);
        relu_split(acc[2*u][2]   + a10.x, acc[2*u][3]   + a10.y, h1, l1);
        relu_split(acc[2*u+1][0] + a01.x, acc[2*u+1][1] + a01.y, h2, l2);
        relu_split(acc[2*u+1][2] + a11.x, acc[2*u+1][3] + a11.y, h3, l3);
        const int fi = (wm * 16 + wg * 8 + u) * 32 + lane;
        AHI[fi] = make_uint4(h0, h1, h2, h3);
        ALO[fi] = make_uint4(l0, l1, l2, l3);
    }
}

// ============================ main kernel ====================================
__global__ void __launch_bounds__(NT, 1)
surface_kernel(
    const float* __restrict__ centers,  const float* __restrict__ enc_g,
    const float* __restrict__ enc_node, const float* __restrict__ neighbors,
    const float* __restrict__ normals,  const float* __restrict__ neigh_normals,
    const float* __restrict__ areas,    const float* __restrict__ neigh_areas,
    const float* __restrict__ basis_b1, const float* __restrict__ basis_b2,
    const float* __restrict__ agg_b2,   const float* __restrict__ agg_W3,
    const float* __restrict__ agg_b3,   float* __restrict__ out,
    const int n_nodes)
{
    extern __shared__ uint8_t sb[];
    const int t = threadIdx.x;
    const int hf = t >> 8;
    const int th = t & 255;
    const int w  = th >> 5;
    const int lane = t & 31;
    const int wg = w >> 2;
    const int wm = w & 3;
    const int tw = th & 127;
    const int quad = lane >> 2, q4 = lane & 3;
    const int base9 = blockIdx.x * NPC + hf * NPCH;

    uint8_t* sbH = sb + hf * HALF_BYTES;
    uint8_t* sbW = sbH + OFF_W + wg * 16384;
    float* ctxp  = (float*)(sbH + OFF_CTXP);
    float* svt   = ctxp;                       // svol temp (preamble only)
    float* arowp = (float*)(sbH + OFF_ARP);
    float* arow  = (float*)(sbH + OFF_ARW);
    float* invd  = (float*)(sbH + OFF_INVD);
    float* dsum  = (float*)(sbH + OFF_DSUM);
    uint4* AHI   = (uint4*)(sbH + OFF_AHI);
    uint4* ALO   = (uint4*)(sbH + OFF_ALO);
    const int barw = 1 + hf * 2 + wg;
    const int barh = 5 + hf;

    // ---- preamble: build 64 vol rows into svt ----
    if (th < 64) {
        float f[8] = {0.f,0.f,0.f,0.f,0.f,0.f,0.f,0.f};
        const int nl = th / PP, p = th % PP;
        const int node = base9 + nl;
        if (th < NPCH * PP && node < n_nodes) {
            if (p == 0) {
                f[0]=centers[node*3+0]; f[1]=centers[node*3+1]; f[2]=centers[node*3+2];
                f[3]=normals[node*3+0]; f[4]=normals[node*3+1]; f[5]=normals[node*3+2];
                f[6]=logf(areas[node]) * 0.1f;
            } else {
                const int nb = node * NK + (p - 1);
                f[0]=neighbors[nb*3+0]+1e-6f; f[1]=neighbors[nb*3+1]+1e-6f;
                f[2]=neighbors[nb*3+2]+1e-6f;
                f[3]=neigh_normals[nb*3+0]+1e-6f; f[4]=neigh_normals[nb*3+1]+1e-6f;
                f[5]=neigh_normals[nb*3+2]+1e-6f;
                f[6]=logf(neigh_areas[nb]) * 0.1f + 1e-6f;
            }
        }
#pragma unroll
        for (int q = 0; q < 8; q++) svt[th * 8 + q] = f[q];
    }
    BARN(barh, 256);
    if (th < NPCH * NK) {
        const int nl = th / NK, j = th % NK;
        float d2 = 0.f;
#pragma unroll
        for (int q = 0; q < 7; q++) {
            const float d = svt[(nl*7)*8 + q] - svt[(nl*7 + 1 + j)*8 + q];
            d2 += d * d;
        }
        invd[nl * 8 + j] = 1.f / sqrtf(d2);
    }
    BARN(barh, 256);
    if (th < NPCH) {
        float s = 0.f;
#pragma unroll
        for (int j = 0; j < NK; j++) s += invd[th * 8 + j];
        dsum[th] = s;
    }
    // ---- vol A-frags (slots 64..67), built by wg0 warps ----
    if (wg == 0) {
        const int r0m = wm * 16 + quad, r1m = r0m + 8;
        const int klo = 2 * q4;
        float x0 = (klo < 7)     ? svt[r0m*8 + klo]     : 0.f;
        float x1 = (klo + 1 < 7) ? svt[r0m*8 + klo + 1] : 0.f;
        float y0 = (klo < 7)     ? svt[r1m*8 + klo]     : 0.f;
        float y1 = (klo + 1 < 7) ? svt[r1m*8 + klo + 1] : 0.f;
        uint32_t hx, lx, hy, ly;
        plain_split(x0, x1, hx, lx);
        plain_split(y0, y1, hy, ly);
        AHI[(64 + wm) * 32 + lane] = make_uint4(hx, hy, 0u, 0u);
        ALO[(64 + wm) * 32 + lane] = make_uint4(lx, ly, 0u, 0u);
    }
    // prefetch v=0 ctx chunks
    prefetchW(sbW, g_wB + CTXOFF + (size_t)wg * 12 * CHK, tw);
    BARN(barh, 256);

    const int r0m = wm * 16 + quad;
    float acc[16][4];

#pragma unroll 1
    for (int v = 0; v < V_; v++) {
        const uint8_t* wv = g_wB + (size_t)v * VSTRIDE;

        // ---- (a) ctx A-frags (slots 0..11): M=16 rows = nodes ----
#pragma unroll
        for (int rep = 0; rep < 2; rep++) {
            const int slot = w + rep * 8;
            if (slot < 12) {
                const int klo = slot * 16 + 2 * q4;
                const int khi = klo + 8;
                float2 v00, v10, v01, v11;
                auto feat2 = [&](int node_l, int k) -> float2 {
                    const int node = base9 + node_l;
                    if (node_l < NPCH && node < n_nodes && k < 160) {
                        if (k < 32) return *(const float2*)(enc_node + (size_t)node*32 + k);
                        return *(const float2*)(enc_g + (size_t)node*128 + (k - 32));
                    }
                    return make_float2(0.f, 0.f);
                };
                v00 = feat2(quad, klo);     v10 = feat2(quad + 8, klo);
                v01 = feat2(quad, khi);     v11 = feat2(quad + 8, khi);
                uint32_t h0,l0,h1,l1,h2,l2,h3,l3;
                plain_split(v00.x, v00.y, h0, l0);
                plain_split(v10.x, v10.y, h1, l1);
                plain_split(v01.x, v01.y, h2, l2);
                plain_split(v11.x, v11.y, h3, l3);
                AHI[slot * 32 + lane] = make_uint4(h0, h1, h2, h3);
                ALO[slot * 32 + lane] = make_uint4(l0, l1, l2, l3);
            }
        }
        BARN(barh, 256);

        // ---- ctx GEMM ----
#pragma unroll
        for (int i = 0; i < 4; i++)
#pragma unroll
            for (int j = 0; j < 4; j++) acc[i][j] = 0.f;
        run_ml<0>(sbW, wv + CTXOFF + (size_t)wg * 12 * CHK, tw, barw, AHI, ALO, lane, wm, acc);
        prefetchW(sbW, wv + L1OFF + (size_t)wg * 4 * CHK, tw);
        // ctx epilogue: warp (wm, wg) owns cols wg*128 + wm*32 .. +32
        {
            const int ccb = wg * 128 + wm * 32;
            const int node0 = quad, node1 = quad + 8;
#pragma unroll
            for (int f = 0; f < 4; f++) {
                const int col = ccb + f * 8 + 2 * q4;
                const float2 cst = *(const float2*)(&g_cst3[v][col]);
                if (node0 < NPCH && base9 + node0 < n_nodes)
                    *(float2*)(ctxp + node0 * 260 + col) =
                        make_float2(acc[f][0] + cst.x, acc[f][1] + cst.y);
                if (node1 < NPCH && base9 + node1 < n_nodes)
                    *(float2*)(ctxp + node1 * 260 + col) =
                        make_float2(acc[f][2] + cst.x, acc[f][3] + cst.y);
            }
        }
        BARN(barh, 256);

        // ---- L1 (vol @ W1) ----
#pragma unroll
        for (int i = 0; i < 16; i++)
#pragma unroll
            for (int j = 0; j < 4; j++) acc[i][j] = 0.f;
        run_ml<1>(sbW, wv + L1OFF + (size_t)wg * 4 * CHK, tw, barw, AHI, ALO, lane, wm, acc);
        prefetchW(sbW, wv + L2OFF + (size_t)wg * 16 * CHK, tw);
        BARN(barh, 256);
        epiA<0>(sbH, acc, basis_b1 + v * 256, wm, wg, lane);
        BARN(barh, 256);

        // ---- L2 ----
#pragma unroll
        for (int i = 0; i < 16; i++)
#pragma unroll
            for (int j = 0; j < 4; j++) acc[i][j] = 0.f;
        run_ml<2>(sbW, wv + L2OFF + (size_t)wg * 16 * CHK, tw, barw, AHI, ALO, lane, wm, acc);
        prefetchW(sbW, wv + L3OFF + (size_t)wg * 16 * CHK, tw);
        BARN(barh, 256);
        epiA<0>(sbH, acc, basis_b2 + v * 256, wm, wg, lane);
        BARN(barh, 256);

        // ---- L3 ----
#pragma unroll
        for (int i = 0; i < 16; i++)
#pragma unroll
            for (int j = 0; j < 4; j++) acc[i][j] = 0.f;
        run_ml<2>(sbW, wv + L3OFF + (size_t)wg * 16 * CHK, tw, barw, AHI, ALO, lane, wm, acc);
        prefetchW(sbW, wv + L4OFF + (size_t)wg * 8 * CHK, tw);
        BARN(barh, 256);
        epiA<1>(sbH, acc, ctxp, wm, wg, lane);
        BARN(barh, 256);

        // ---- L4 + L5 ----
#pragma unroll
        for (int i = 0; i < 8; i++)
#pragma unroll
            for (int j = 0; j < 4; j++) acc[i][j] = 0.f;
        run_ml<3>(sbW, wv + L4OFF + (size_t)wg * 8 * CHK, tw, barw, AHI, ALO, lane, wm, acc);
        if (v + 1 < V_)
            prefetchW(sbW, wv + VSTRIDE + CTXOFF + (size_t)wg * 12 * CHK, tw);
        {
            float s0 = 0.f, s1 = 0.f;
#pragma unroll
            for (int f = 0; f < 8; f++) {
                const int c0 = wg * 64 + f * 8 + 2 * q4;
                const float2 w3v = __ldg((const float2*)(agg_W3 + v * 128 + c0));
                const float2 b4v = __ldg((const float2*)(agg_b2 + v * 128 + c0));
                s0 += fmaxf(acc[f][0] + b4v.x, 0.f) * w3v.x
                    + fmaxf(acc[f][1] + b4v.y, 0.f) * w3v.y;
                s1 += fmaxf(acc[f][2] + b4v.x, 0.f) * w3v.x
                    + fmaxf(acc[f][3] + b4v.y, 0.f) * w3v.y;
            }
            s0 += __shfl_xor_sync(0xffffffffu, s0, 1);
            s0 += __shfl_xor_sync(0xffffffffu, s0, 2);
            s1 += __shfl_xor_sync(0xffffffffu, s1, 1);
            s1 += __shfl_xor_sync(0xffffffffu, s1, 2);
            if (q4 == 0) {
                arowp[wg * 64 + r0m] = s0;
                arowp[wg * 64 + r0m + 8] = s1;
            }
        }
        BARN(barh, 256);
        if (th < 64) arow[th] = arowp[th] + arowp[64 + th] + __ldg(agg_b3 + v);
        BARN(barh, 256);
        if (th < NPCH) {
            const int node = base9 + th;
            if (node < n_nodes) {
                const float c = arow[th * 7];
                float s = 0.f;
#pragma unroll
                for (int j = 0; j < NK; j++) s += arow[th * 7 + 1 + j] * invd[th * 8 + j];
                out[node * V_ + v] = 0.5f * c + 0.5f * s / dsum[th];
            }
        }
        BARN(barh, 256);
    }
}

// ============================ launcher =======================================
extern "C" void kernel_launch(void* const* d_in, const int* in_sizes, int n_in,
                              void* d_out, int out_size)
{
    const float* centers       = (const float*)d_in[0];
    const float* enc_g         = (const float*)d_in[1];
    const float* enc_node      = (const float*)d_in[2];
    const float* neighbors     = (const float*)d_in[3];
    const float* normals       = (const float*)d_in[4];
    const float* neigh_normals = (const float*)d_in[5];
    const float* areas         = (const float*)d_in[6];
    const float* neigh_areas   = (const float*)d_in[7];
    const float* gpv           = (const float*)d_in[8];
    const float* gpr           = (const float*)d_in[9];
    const float* param_W       = (const float*)d_in[10];
    const float* param_b       = (const float*)d_in[11];
    const float* basis_W1      = (const float*)d_in[12];
    const float* basis_b1      = (const float*)d_in[13];
    const float* basis_W2      = (const float*)d_in[14];
    const float* basis_b2      = (const float*)d_in[15];
    const float* agg_W1        = (const float*)d_in[16];
    const float* agg_b1        = (const float*)d_in[17];
    const float* agg_W2        = (const float*)d_in[18];
    const float* agg_b2        = (const float*)d_in[19];
    const float* agg_W3        = (const float*)d_in[20];
    const float* agg_b3        = (const float*)d_in[21];
    float* out = (float*)d_out;

    const int n_nodes = in_sizes[0] / 3;
    const int grid = (n_nodes + NPC - 1) / NPC;

    cudaFuncSetAttribute(surface_kernel,
                         cudaFuncAttributeMaxDynamicSharedMemorySize, SMEM_BYTES);

    cst3_kernel<<<1, 256>>>(gpv, gpr, param_W, param_b, agg_W1, agg_b1);
    wconv_kernel<<<1792, 1024>>>(basis_W1, basis_W2, agg_W1, agg_W2);
    surface_kernel<<<grid, NT, SMEM_BYTES>>>(
        centers, enc_g, enc_node, neighbors, normals, neigh_normals,
        areas, neigh_areas,
        basis_b1, basis_b2, agg_b2, agg_W3, agg_b3, out, n_nodes);
}

// round 9
// speedup vs baseline: 3.7070x; 3.7070x over previous
#include <cuda_runtime.h>
#include <cuda_bf16.h>
#include <math.h>
#include <stdint.h>

constexpr int V_ = 4;
constexpr int NK = 6;
constexpr int PP = 7;
constexpr int NPC = 18;
constexpr int ROWS_ = 126;
constexpr int NT = 512;

// weight blob per v, per-warpgroup streams of [128n][64k] (16KB) chunks
// (L4: [64n][64k] 8KB). Per wg: L2 8 chunks, L3 8, L4 8, CTX 6.
constexpr int CB  = 16384;
constexpr int CB4 = 8192;
constexpr int L3OFF  = 16 * CB;               // 262144
constexpr int L4OFF  = L3OFF + 16 * CB;       // 524288
constexpr int CTXOFF = L4OFF + 16 * CB4;      // 655360
constexpr int VSTRIDE = CTXOFF + 12 * CB;     // 851968

__device__ uint8_t g_wB[(size_t)V_ * VSTRIDE];
__device__ float   g_cst3[V_][256];

// ---- smem byte offsets ----
constexpr int OFF_W    = 0;        // 65536: wg0 [0,32K), wg1 [32K,64K)
constexpr int OFF_AHI  = 65536;    // 65536 (A hi frags: 128 slots x 512B)
constexpr int OFF_ALO  = 131072;   // 65536
constexpr int OFF_CTXP = 196608;   // 18*260*4 = 18720
constexpr int OFF_SVOL = 215328;   // 4096 (svol in preamble; arowp after)
constexpr int OFF_W1S  = 219424;   // 7168
constexpr int OFF_B1S  = 226592;   // 1024
constexpr int OFF_B2S  = 227616;   // 1024
constexpr int OFF_B4S  = 228640;   // 512
constexpr int OFF_W3S  = 229152;   // 512
constexpr int OFF_ARW  = 230688;   // 512
constexpr int OFF_INVD = 231200;   // 576
constexpr int OFF_DSUM = 231776;   // 96
constexpr int SMEM_BYTES = 231872;

// ============================ PTX helpers ====================================
__device__ __forceinline__ uint32_t su32(const void* p) {
    return (uint32_t)__cvta_generic_to_shared(p);
}
__device__ __forceinline__ void cp16(uint8_t* s, const uint8_t* g) {
    uint32_t sa = su32(s);
    asm volatile("cp.async.cg.shared.global [%0], [%1], 16;" :: "r"(sa), "l"(g));
}
#define CP_COMMIT() asm volatile("cp.async.commit_group;" ::: "memory")
#define CP_WAIT1()  asm volatile("cp.async.wait_group 1;" ::: "memory")
#define CP_WAIT0()  asm volatile("cp.async.wait_group 0;" ::: "memory")
// per-warpgroup named barrier (ids 1,2), 256 threads each
#define BARW(g) asm volatile("bar.sync %0, %1;" :: "r"((g) + 1), "r"(256) : "memory")

#define MMA_BF16(acc, a, b0, b1) asm volatile( \
    "mma.sync.aligned.m16n8k16.row.col.f32.bf16.bf16.f32 " \
    "{%0,%1,%2,%3}, {%4,%5,%6,%7}, {%8,%9}, {%0,%1,%2,%3};" \
    : "+f"((acc)[0]), "+f"((acc)[1]), "+f"((acc)[2]), "+f"((acc)[3]) \
    : "r"((a).x), "r"((a).y), "r"((a).z), "r"((a).w), "r"(b0), "r"(b1))

#define LDSM4(r0, r1, r2, r3, addr) asm volatile( \
    "ldmatrix.sync.aligned.m8n8.x4.shared.b16 {%0,%1,%2,%3}, [%4];" \
    : "=r"(r0), "=r"(r1), "=r"(r2), "=r"(r3) : "r"(addr))

__device__ __forceinline__ void relu_split(float x, float y, uint32_t& h, uint32_t& l) {
    x = fmaxf(x, 0.f); y = fmaxf(y, 0.f);
    __nv_bfloat162 hb = __float22bfloat162_rn(make_float2(x, y));
    float2 hf = __bfloat1622float2(hb);
    __nv_bfloat162 lb = __float22bfloat162_rn(make_float2(x - hf.x, y - hf.y));
    h = *reinterpret_cast<uint32_t*>(&hb);
    l = *reinterpret_cast<uint32_t*>(&lb);
}
__device__ __forceinline__ void plain_split(float x, float y, uint32_t& h, uint32_t& l) {
    __nv_bfloat162 hb = __float22bfloat162_rn(make_float2(x, y));
    float2 hf = __bfloat1622float2(hb);
    __nv_bfloat162 lb = __float22bfloat162_rn(make_float2(x - hf.x, y - hf.y));
    h = *reinterpret_cast<uint32_t*>(&hb);
    l = *reinterpret_cast<uint32_t*>(&lb);
}
__device__ __forceinline__ void ffma2s(float2& d, float a, float2 b) {
    unsigned long long dd = *reinterpret_cast<unsigned long long*>(&d);
    float2 av = make_float2(a, a);
    unsigned long long aa = *reinterpret_cast<unsigned long long*>(&av);
    unsigned long long bb = *reinterpret_cast<unsigned long long*>(&b);
    asm("fma.rn.f32x2 %0, %1, %2, %0;" : "+l"(dd) : "l"(aa), "l"(bb));
    d = *reinterpret_cast<float2*>(&dd);
}

// ===================== side kernel 1: cst3 ===================================
__global__ void cst3_kernel(const float* __restrict__ gpv, const float* __restrict__ gpr,
                            const float* __restrict__ pW, const float* __restrict__ pb,
                            const float* __restrict__ aW1, const float* __restrict__ ab1)
{
    __shared__ float pe[32];
    const int t = threadIdx.x;
    const float p0 = gpv[0] / gpr[0], p1 = gpv[1] / gpr[1];
    if (t < 32) pe[t] = fmaxf(pb[t] + p0 * pW[t] + p1 * pW[32 + t], 0.f);
    __syncthreads();
    for (int idx = t; idx < V_ * 256; idx += blockDim.x) {
        const int v = idx >> 8, c = idx & 255;
        const float* W = aW1 + ((size_t)v * 448 + 416) * 256 + c;
        float s = ab1[v * 256 + c];
#pragma unroll
        for (int k = 0; k < 32; k++) s += pe[k] * W[(size_t)k * 256];
        g_cst3[v][c] = s;
    }
}

// ===================== side kernel 2: weight convert (same blob as R6) =======
__global__ void wconv_kernel(const float* __restrict__ bW2,
                             const float* __restrict__ aW1,
                             const float* __restrict__ aW2)
{
    constexpr int PERV = 131072 + 131072 + 65536 + 98304;   // 425984
    const int total = V_ * PERV;
    for (int idx = blockIdx.x * blockDim.x + threadIdx.x; idx < total;
         idx += gridDim.x * blockDim.x) {
        const int v = idx / PERV;
        int e = idx % PERV;
        size_t dst;
        int n_local, kl;
        bool hiC;
        float w;
        if (e < 131072) {                       // L2
            const int wg = e >> 16, r = e & 65535;
            const int c = r >> 13, rr = r & 8191;
            n_local = rr >> 6; kl = rr & 63;
            const int n = wg * 128 + n_local, k = (c & 3) * 64 + kl;
            hiC = (c < 4);
            w = bW2[((size_t)v * 256 + k) * 256 + n];
            dst = (size_t)wg * 8 * CB + (size_t)c * CB;
        } else if (e < 262144) {                // L3
            e -= 131072;
            const int wg = e >> 16, r = e & 65535;
            const int c = r >> 13, rr = r & 8191;
            n_local = rr >> 6; kl = rr & 63;
            const int n = wg * 128 + n_local, k = (c & 3) * 64 + kl;
            hiC = (c < 4);
            w = aW1[((size_t)v * 448 + k) * 256 + n];
            dst = L3OFF + (size_t)wg * 8 * CB + (size_t)c * CB;
        } else if (e < 327680) {                // L4
            e -= 262144;
            const int wg = e >> 15, r = e & 32767;
            const int c = r >> 12, rr = r & 4095;
            n_local = rr >> 6; kl = rr & 63;
            const int n = wg * 64 + n_local, k = (c & 3) * 64 + kl;
            hiC = (c < 4);
            w = aW2[((size_t)v * 256 + k) * 128 + n];
            dst = L4OFF + (size_t)wg * 8 * CB4 + (size_t)c * CB4;
        } else {                                // CTX (K padded 160->192)
            e -= 327680;
            const int wg2 = e / 49152, r2 = e % 49152;
            const int c = r2 >> 13, rr = r2 & 8191;
            n_local = rr >> 6; kl = rr & 63;
            const int n = wg2 * 128 + n_local, k = (c % 3) * 64 + kl;
            hiC = (c < 3);
            w = (k < 160) ? aW1[((size_t)v * 448 + 256 + k) * 256 + n] : 0.f;
            dst = CTXOFF + (size_t)wg2 * 6 * CB + (size_t)c * CB;
        }
        __nv_bfloat16 hi = __float2bfloat16_rn(w);
        __nv_bfloat16 val = hiC ? hi : __float2bfloat16_rn(w - __bfloat162float(hi));
        uint8_t* p = g_wB + (size_t)v * VSTRIDE + dst
                   + n_local * 128 + (((uint32_t)(kl * 2)) ^ (((uint32_t)n_local & 7) << 4));
        *reinterpret_cast<__nv_bfloat16*>(p) = val;
    }
}

// ===================== per-wg copy / prefetch ================================
template <int CBT>
__device__ __forceinline__ void copy_chunkT(uint8_t* dst, const uint8_t* src, int tw) {
    constexpr int NCP = CBT / 16 / 256;
#pragma unroll
    for (int i = 0; i < NCP; i++)
        cp16(dst + (tw + i * 256) * 16, src + (size_t)(tw + i * 256) * 16);
}
template <int CBT>
__device__ __forceinline__ void prefetchT(uint8_t* sbW, const uint8_t* wsrc, int tw) {
    copy_chunkT<CBT>(sbW, wsrc, tw);             CP_COMMIT();
    copy_chunkT<CBT>(sbW + CBT, wsrc + CBT, tw); CP_COMMIT();
}

// ===================== mainloop ==============================================
// MODE 0: ctx (6 chunks, warp = 1Mfrag x 4Nfrag via cwm/cwn)
// MODE 2: big 256-col layer (8 chunks, warp = 2Mfrag x 8Nfrag via m2/n2)
// MODE 3: L4 128-col layer (8 chunks of 8KB, warp = 2Mfrag x 4Nfrag)
template <int MODE>
__device__ __forceinline__ void run_ml(
    uint8_t* sbW, const uint8_t* wsrc, int tw, int wg, int lane, int widg,
    const uint4* __restrict__ AHI, const uint4* __restrict__ ALO, float (*acc)[4])
{
    constexpr int NCHUNK = (MODE == 0) ? 6 : 8;
    constexpr int CBT = (MODE == 3) ? CB4 : CB;
    const uint32_t swzc = ((uint32_t)lane & 7) << 4;
    const int lanerow = 8 * ((lane >> 4) & 1) + (lane & 7);
    const int kadd = ((lane >> 3) & 1) * 8;
    const int m2 = widg & 3, n2 = widg >> 2;
    const int cwm = widg & 1, cwn = widg >> 1;
#pragma unroll 1
    for (int c = 0; c < NCHUNK; c++) {
        if (c < NCHUNK - 1) CP_WAIT1(); else CP_WAIT0();
        BARW(wg);
        const uint32_t wb = su32(sbW + (c & 1) * CBT);
        const bool hiB = (c < NCHUNK / 2);
        const int fkb = (c % (NCHUNK / 2)) * 4;
#pragma unroll
        for (int s = 0; s < 4; s++) {
            const int fk = fkb + s;
            const int koff = s * 16 + kadd;
            if constexpr (MODE == 0) {
                const uint4 ah = AHI[(cwm * 12 + fk) * 32 + lane];
                uint4 al = make_uint4(0, 0, 0, 0);
                if (hiB) al = ALO[(cwm * 12 + fk) * 32 + lane];
                const uint32_t ba = wb + (uint32_t)((cwn * 32 + lanerow) * 128)
                                  + (((uint32_t)(koff * 2)) ^ swzc);
#pragma unroll
                for (int jj = 0; jj < 2; jj++) {
                    uint32_t b0, b1, b2, b3;
                    LDSM4(b0, b1, b2, b3, ba + jj * 2048);
                    MMA_BF16(acc[2 * jj],     ah, b0, b1);
                    MMA_BF16(acc[2 * jj + 1], ah, b2, b3);
                    if (hiB) {
                        MMA_BF16(acc[2 * jj],     al, b0, b1);
                        MMA_BF16(acc[2 * jj + 1], al, b2, b3);
                    }
                }
            } else if constexpr (MODE == 2) {
                const int sl0 = (m2 * 2) * 16 + fk, sl1 = (m2 * 2 + 1) * 16 + fk;
                const uint4 a0 = AHI[sl0 * 32 + lane];
                const uint4 a1 = AHI[sl1 * 32 + lane];
                uint4 l0 = make_uint4(0, 0, 0, 0), l1 = l0;
                if (hiB) { l0 = ALO[sl0 * 32 + lane]; l1 = ALO[sl1 * 32 + lane]; }
                const uint32_t ba = wb + (uint32_t)((n2 * 64 + lanerow) * 128)
                                  + (((uint32_t)(koff * 2)) ^ swzc);
#pragma unroll
                for (int jj = 0; jj < 4; jj++) {
                    uint32_t b0, b1, b2, b3;
                    LDSM4(b0, b1, b2, b3, ba + jj * 2048);
                    MMA_BF16(acc[jj * 2],         a0, b0, b1);
                    MMA_BF16(acc[jj * 2 + 1],     a0, b2, b3);
                    MMA_BF16(acc[8 + jj * 2],     a1, b0, b1);
                    MMA_BF16(acc[8 + jj * 2 + 1], a1, b2, b3);
                    if (hiB) {
                        MMA_BF16(acc[jj * 2],         l0, b0, b1);
                        MMA_BF16(acc[jj * 2 + 1],     l0, b2, b3);
                        MMA_BF16(acc[8 + jj * 2],     l1, b0, b1);
                        MMA_BF16(acc[8 + jj * 2 + 1], l1, b2, b3);
                    }
                }
            } else {
                const int sl0 = (m2 * 2) * 16 + fk, sl1 = (m2 * 2 + 1) * 16 + fk;
                const uint4 a0 = AHI[sl0 * 32 + lane];
                const uint4 a1 = AHI[sl1 * 32 + lane];
                uint4 l0 = make_uint4(0, 0, 0, 0), l1 = l0;
                if (hiB) { l0 = ALO[sl0 * 32 + lane]; l1 = ALO[sl1 * 32 + lane]; }
                const uint32_t ba = wb + (uint32_t)((n2 * 32 + lanerow) * 128)
                                  + (((uint32_t)(koff * 2)) ^ swzc);
#pragma unroll
                for (int jj = 0; jj < 2; jj++) {
                    uint32_t b0, b1, b2, b3;
                    LDSM4(b0, b1, b2, b3, ba + jj * 2048);
                    MMA_BF16(acc[jj * 2],         a0, b0, b1);
                    MMA_BF16(acc[jj * 2 + 1],     a0, b2, b3);
                    MMA_BF16(acc[4 + jj * 2],     a1, b0, b1);
                    MMA_BF16(acc[4 + jj * 2 + 1], a1, b2, b3);
                    if (hiB) {
                        MMA_BF16(acc[jj * 2],         l0, b0, b1);
                        MMA_BF16(acc[jj * 2 + 1],     l0, b2, b3);
                        MMA_BF16(acc[4 + jj * 2],     l1, b0, b1);
                        MMA_BF16(acc[4 + jj * 2 + 1], l1, b2, b3);
                    }
                }
            }
        }
        BARW(wg);
        if (c + 2 < NCHUNK) {
            copy_chunkT<CBT>(sbW + (c & 1) * CBT, wsrc + (size_t)(c + 2) * CBT, tw);
            CP_COMMIT();
        }
    }
}

// ===================== epilogue: C frags -> A frags (4Mx2N tiling) ==========
template <int MODE>
__device__ __forceinline__ void epiA2(
    uint8_t* sbH, float (*acc)[4], const float* __restrict__ addv,
    int widg, int wg, int lane)
{
    uint4* AHI = (uint4*)(sbH + OFF_AHI);
    uint4* ALO = (uint4*)(sbH + OFF_ALO);
    const int quad = lane >> 2, q4 = lane & 3;
    const int m2 = widg & 3, n2 = widg >> 2;
#pragma unroll
    for (int e = 0; e < 2; e++) {
        const int mfrag = m2 * 2 + e;
        const int r0 = mfrag * 16 + quad;
        int n0 = r0 / 7;       if (n0 > 17) n0 = 17;
        int n1 = (r0 + 8) / 7; if (n1 > 17) n1 = 17;
#pragma unroll
        for (int jj = 0; jj < 4; jj++) {
            const int fk = wg * 8 + n2 * 4 + jj;
            const int c0 = fk * 16 + 2 * q4;
            const int c2 = c0 + 8;
            float2 a00, a01, a10, a11;
            if constexpr (MODE == 0) {
                a00 = *(const float2*)(addv + c0);
                a01 = *(const float2*)(addv + c2);
                a10 = a00; a11 = a01;
            } else {
                a00 = *(const float2*)(addv + n0 * 260 + c0);
                a01 = *(const float2*)(addv + n0 * 260 + c2);
                a10 = *(const float2*)(addv + n1 * 260 + c0);
                a11 = *(const float2*)(addv + n1 * 260 + c2);
            }
            const float* A = acc[e * 8 + jj * 2];
            const float* B = acc[e * 8 + jj * 2 + 1];
            uint32_t h0, l0, h1, l1, h2, l2, h3, l3;
            relu_split(A[0] + a00.x, A[1] + a00.y, h0, l0);
            relu_split(A[2] + a10.x, A[3] + a10.y, h1, l1);
            relu_split(B[0] + a01.x, B[1] + a01.y, h2, l2);
            relu_split(B[2] + a11.x, B[3] + a11.y, h3, l3);
            const int fi = (mfrag * 16 + fk) * 32 + lane;
            AHI[fi] = make_uint4(h0, h1, h2, h3);
            ALO[fi] = make_uint4(l0, l1, l2, l3);
        }
    }
}

// ============================ main kernel ====================================
__global__ void __launch_bounds__(NT, 1)
surface_kernel(
    const float* __restrict__ centers,  const float* __restrict__ enc_g,
    const float* __restrict__ enc_node, const float* __restrict__ neighbors,
    const float* __restrict__ normals,  const float* __restrict__ neigh_normals,
    const float* __restrict__ areas,    const float* __restrict__ neigh_areas,
    const float* __restrict__ basis_W1, const float* __restrict__ basis_b1,
    const float* __restrict__ basis_b2, const float* __restrict__ agg_b2,
    const float* __restrict__ agg_W3,   const float* __restrict__ agg_b3,
    float* __restrict__ out, const int n_nodes)
{
    extern __shared__ uint8_t sb[];
    const int t = threadIdx.x;
    const int wid = t >> 5, lane = t & 31;
    const int wg = wid >> 3;           // warpgroup 0/1 == column half
    const int widg = wid & 7;          // warp within wg
    const int tw = t & 255;
    const int quad = lane >> 2, q4 = lane & 3;
    const int base = blockIdx.x * NPC;

    float* ctxps = (float*)(sb + OFF_CTXP);
    float* svol  = (float*)(sb + OFF_SVOL);
    float* arowp = (float*)(sb + OFF_SVOL);    // overlays svol (dead after preamble)
    float* W1s   = (float*)(sb + OFF_W1S);
    float* b1s   = (float*)(sb + OFF_B1S);
    float* b2s   = (float*)(sb + OFF_B2S);
    float* b4s   = (float*)(sb + OFF_B4S);
    float* w3s   = (float*)(sb + OFF_W3S);
    float* arow  = (float*)(sb + OFF_ARW);
    float* invd  = (float*)(sb + OFF_INVD);
    float* dsum  = (float*)(sb + OFF_DSUM);
    uint8_t* sbW = sb + OFF_W + wg * 32768;
    const uint4* AHIc = (const uint4*)(sb + OFF_AHI);
    const uint4* ALOc = (const uint4*)(sb + OFF_ALO);

    // prefetch v=0 ctx chunks (per wg stream)
    prefetchT<CB>(sbW, g_wB + CTXOFF + (size_t)wg * 6 * CB, tw);

    // ---- build vol rows ----
    if (t < 128) {
        float f[8] = {0.f,0.f,0.f,0.f,0.f,0.f,0.f,0.f};
        const int nl = t / PP, p = t % PP;
        const int node = base + nl;
        if (t < ROWS_ && node < n_nodes) {
            if (p == 0) {
                f[0]=centers[node*3+0]; f[1]=centers[node*3+1]; f[2]=centers[node*3+2];
                f[3]=normals[node*3+0]; f[4]=normals[node*3+1]; f[5]=normals[node*3+2];
                f[6]=logf(areas[node]) * 0.1f;
            } else {
                const int nb = node * NK + (p - 1);
                f[0]=neighbors[nb*3+0]+1e-6f; f[1]=neighbors[nb*3+1]+1e-6f;
                f[2]=neighbors[nb*3+2]+1e-6f;
                f[3]=neigh_normals[nb*3+0]+1e-6f; f[4]=neigh_normals[nb*3+1]+1e-6f;
                f[5]=neigh_normals[nb*3+2]+1e-6f;
                f[6]=logf(neigh_areas[nb]) * 0.1f + 1e-6f;
            }
        }
#pragma unroll
        for (int q = 0; q < 8; q++) svol[t * 8 + q] = f[q];
    }
    __syncthreads();
    if (t < NPC * NK) {
        const int nl = t / NK, j = t % NK;
        float d2 = 0.f;
#pragma unroll
        for (int q = 0; q < 7; q++) {
            const float d = svol[(nl*7)*8 + q] - svol[(nl*7 + 1 + j)*8 + q];
            d2 += d * d;
        }
        invd[nl * 8 + j] = 1.f / sqrtf(d2);
    }
    __syncthreads();
    if (t < NPC) {
        float s = 0.f;
#pragma unroll
        for (int j = 0; j < NK; j++) s += invd[t * 8 + j];
        dsum[t] = s;
    }

    const int r0m = 16 * widg + quad;
    float sv0[7], sv1[7];
#pragma unroll
    for (int q = 0; q < 7; q++) {
        sv0[q] = svol[r0m * 8 + q];
        sv1[q] = svol[(r0m + 8) * 8 + q];
    }
    __syncthreads();   // svol reads done; arowp may overwrite later

    float acc[16][4];

#pragma unroll 1
    for (int v = 0; v < V_; v++) {
        const uint8_t* wv = g_wB + (size_t)v * VSTRIDE;
        // per-v constants
        for (int i = t; i < 1792; i += NT) W1s[i] = __ldg(basis_W1 + (size_t)v * 1792 + i);
        if (t < 256) { b1s[t] = __ldg(basis_b1 + v * 256 + t);
                       b2s[t] = __ldg(basis_b2 + v * 256 + t); }
        else if (t < 384) { b4s[t-256] = __ldg(agg_b2 + v * 128 + (t-256)); }
        else { w3s[t-384] = __ldg(agg_W3 + v * 128 + (t-384)); }

        // ---- build ctx A frags (slots 0..23; M=32 rows, K padded to 192) ----
        {
            uint4* AHI = (uint4*)(sb + OFF_AHI);
            uint4* ALO = (uint4*)(sb + OFF_ALO);
#pragma unroll
            for (int rep = 0; rep < 2; rep++) {
                const int slot = wid + rep * 16;
                if (slot < 24) {
                    const int fm = slot / 12, fk = slot % 12;
                    const int rr0 = fm * 16 + quad, rr1 = rr0 + 8;
                    const int cc0 = fk * 16 + 2 * q4, cc1 = cc0 + 8;
                    float2 vv[4];
                    const int rs[2] = {rr0, rr1};
                    const int cs[2] = {cc0, cc1};
#pragma unroll
                    for (int a = 0; a < 4; a++) {
                        const int r = rs[a & 1], cc = cs[a >> 1];
                        const int node = base + r;
                        float2 val = make_float2(0.f, 0.f);
                        if (r < NPC && node < n_nodes && cc < 160) {
                            if (cc < 32) val = *(const float2*)(enc_node + (size_t)node*32 + cc);
                            else         val = *(const float2*)(enc_g + (size_t)node*128 + (cc-32));
                        }
                        vv[a] = val;
                    }
                    uint32_t h[4], l[4];
#pragma unroll
                    for (int a = 0; a < 4; a++) plain_split(vv[a].x, vv[a].y, h[a], l[a]);
                    AHI[slot * 32 + lane] = make_uint4(h[0], h[1], h[2], h[3]);
                    ALO[slot * 32 + lane] = make_uint4(l[0], l[1], l[2], l[3]);
                }
            }
        }
        __syncthreads();

        // ---- ctx GEMM (warp = 1Mfrag x 4Nfrag) ----
        {
#pragma unroll
            for (int i = 0; i < 4; i++)
#pragma unroll
                for (int j = 0; j < 4; j++) acc[i][j] = 0.f;
            run_ml<0>(sbW, wv + CTXOFF + (size_t)wg * 6 * CB, tw, wg, lane, widg,
                      AHIc, ALOc, acc);
            prefetchT<CB>(sbW, wv + (size_t)wg * 8 * CB, tw);   // L2 chunks
            // ctx epilogue (warp-private columns)
            const int cwm = widg & 1, cwn = widg >> 1;
            const int rr0 = cwm * 16 + quad;
            const float* cstv = g_cst3[v];
#pragma unroll
            for (int jj = 0; jj < 2; jj++)
#pragma unroll
                for (int e = 0; e < 2; e++) {
                    const int col = wg * 128 + cwn * 32 + jj * 16 + e * 8 + 2 * q4;
                    const float2 cst = *(const float2*)(cstv + col);
                    const float* a = acc[2 * jj + e];
                    if (rr0 < NPC && base + rr0 < n_nodes)
                        *(float2*)(ctxps + rr0 * 260 + col) =
                            make_float2(a[0] + cst.x, a[1] + cst.y);
                    if (rr0 + 8 < NPC && base + rr0 + 8 < n_nodes)
                        *(float2*)(ctxps + (rr0 + 8) * 260 + col) =
                            make_float2(a[2] + cst.x, a[3] + cst.y);
                }
        }
        __syncthreads();   // ctx A slots free; L1 overwrites them

        // ---- L1: produce A frags directly (overlaps L2 weight copies) ----
        {
            uint4* AHI = (uint4*)(sb + OFF_AHI);
            uint4* ALO = (uint4*)(sb + OFF_ALO);
#pragma unroll
            for (int u = 0; u < 8; u++) {
                const int c0 = wg * 128 + 16 * u + 2 * q4;
                const int c2 = c0 + 8;
                float2 a00 = *(const float2*)(b1s + c0);
                float2 a01 = *(const float2*)(b1s + c2);
                float2 a10 = a00, a11 = a01;
#pragma unroll
                for (int q = 0; q < 7; q++) {
                    const float2 w0 = *(const float2*)(W1s + q * 256 + c0);
                    const float2 w2 = *(const float2*)(W1s + q * 256 + c2);
                    ffma2s(a00, sv0[q], w0); ffma2s(a01, sv0[q], w2);
                    ffma2s(a10, sv1[q], w0); ffma2s(a11, sv1[q], w2);
                }
                uint32_t h0, l0, h1, l1, h2, l2, h3, l3;
                relu_split(a00.x, a00.y, h0, l0);
                relu_split(a10.x, a10.y, h1, l1);
                relu_split(a01.x, a01.y, h2, l2);
                relu_split(a11.x, a11.y, h3, l3);
                const int fi = (widg * 16 + 8 * wg + u) * 32 + lane;
                AHI[fi] = make_uint4(h0, h1, h2, h3);
                ALO[fi] = make_uint4(l0, l1, l2, l3);
            }
        }
        __syncthreads();

        // ---- L2 ----
        {
#pragma unroll
            for (int i = 0; i < 16; i++)
#pragma unroll
                for (int j = 0; j < 4; j++) acc[i][j] = 0.f;
            run_ml<2>(sbW, wv + (size_t)wg * 8 * CB, tw, wg, lane, widg,
                      AHIc, ALOc, acc);
            prefetchT<CB>(sbW, wv + L3OFF + (size_t)wg * 8 * CB, tw);
            __syncthreads();   // all warps done reading L1 A-frags
            epiA2<0>(sb, acc, b2s, widg, wg, lane);
        }
        __syncthreads();
        // ---- L3 ----
        {
#pragma unroll
            for (int i = 0; i < 16; i++)
#pragma unroll
                for (int j = 0; j < 4; j++) acc[i][j] = 0.f;
            run_ml<2>(sbW, wv + L3OFF + (size_t)wg * 8 * CB, tw, wg, lane, widg,
                      AHIc, ALOc, acc);
            prefetchT<CB4>(sbW, wv + L4OFF + (size_t)wg * 8 * CB4, tw);
            __syncthreads();
            epiA2<1>(sb, acc, ctxps, widg, wg, lane);
        }
        __syncthreads();
        // ---- L4 + L5 ----
        {
#pragma unroll
            for (int i = 0; i < 8; i++)
#pragma unroll
                for (int j = 0; j < 4; j++) acc[i][j] = 0.f;
            run_ml<3>(sbW, wv + L4OFF + (size_t)wg * 8 * CB4, tw, wg, lane, widg,
                      AHIc, ALOc, acc);
            if (v + 1 < V_)
                prefetchT<CB>(sbW, wv + VSTRIDE + CTXOFF + (size_t)wg * 6 * CB, tw);
            const int m2 = widg & 3, n2 = widg >> 2;
            float s4[4] = {0.f, 0.f, 0.f, 0.f};
#pragma unroll
            for (int e = 0; e < 2; e++)
#pragma unroll
                for (int jj = 0; jj < 2; jj++)
#pragma unroll
                    for (int nf = 0; nf < 2; nf++) {
                        const int c0 = wg * 64 + n2 * 32 + jj * 16 + nf * 8 + 2 * q4;
                        const float2 w3v = *(const float2*)(w3s + c0);
                        const float2 b4v = *(const float2*)(b4s + c0);
                        const float* a = acc[e * 4 + jj * 2 + nf];
                        s4[e * 2 + 0] += fmaxf(a[0] + b4v.x, 0.f) * w3v.x
                                       + fmaxf(a[1] + b4v.y, 0.f) * w3v.y;
                        s4[e * 2 + 1] += fmaxf(a[2] + b4v.x, 0.f) * w3v.x
                                       + fmaxf(a[3] + b4v.y, 0.f) * w3v.y;
                    }
#pragma unroll
            for (int i = 0; i < 4; i++) {
                s4[i] += __shfl_xor_sync(0xffffffffu, s4[i], 1);
                s4[i] += __shfl_xor_sync(0xffffffffu, s4[i], 2);
            }
            __syncthreads();   // arowp region free (prev use done)
            if (q4 == 0) {
                const int p = wg * 2 + n2;
                const int rb = m2 * 32 + quad;
                arowp[p * 128 + rb]      = s4[0];
                arowp[p * 128 + rb + 8]  = s4[1];
                arowp[p * 128 + rb + 16] = s4[2];
                arowp[p * 128 + rb + 24] = s4[3];
            }
        }
        __syncthreads();
        if (t < 128)
            arow[t] = arowp[t] + arowp[128 + t] + arowp[256 + t] + arowp[384 + t]
                    + __ldg(agg_b3 + v);
        __syncthreads();
        if (t < NPC) {
            const int node = base + t;
            if (node < n_nodes) {
                const float c = arow[t * 7];
                float s = 0.f;
#pragma unroll
                for (int j = 0; j < NK; j++) s += arow[t * 7 + 1 + j] * invd[t * 8 + j];
                out[node * V_ + v] = 0.5f * c + 0.5f * s / dsum[t];
            }
        }
        __syncthreads();
    }
}

// ============================ launcher =======================================
extern "C" void kernel_launch(void* const* d_in, const int* in_sizes, int n_in,
                              void* d_out, int out_size)
{
    const float* centers       = (const float*)d_in[0];
    const float* enc_g         = (const float*)d_in[1];
    const float* enc_node      = (const float*)d_in[2];
    const float* neighbors     = (const float*)d_in[3];
    const float* normals       = (const float*)d_in[4];
    const float* neigh_normals = (const float*)d_in[5];
    const float* areas         = (const float*)d_in[6];
    const float* neigh_areas   = (const float*)d_in[7];
    const float* gpv           = (const float*)d_in[8];
    const float* gpr           = (const float*)d_in[9];
    const float* param_W       = (const float*)d_in[10];
    const float* param_b       = (const float*)d_in[11];
    const float* basis_W1      = (const float*)d_in[12];
    const float* basis_b1      = (const float*)d_in[13];
    const float* basis_W2      = (const float*)d_in[14];
    const float* basis_b2      = (const float*)d_in[15];
    const float* agg_W1        = (const float*)d_in[16];
    const float* agg_b1        = (const float*)d_in[17];
    const float* agg_W2        = (const float*)d_in[18];
    const float* agg_b2        = (const float*)d_in[19];
    const float* agg_W3        = (const float*)d_in[20];
    const float* agg_b3        = (const float*)d_in[21];
    float* out = (float*)d_out;

    const int n_nodes = in_sizes[0] / 3;
    const int grid = (n_nodes + NPC - 1) / NPC;

    cudaFuncSetAttribute(surface_kernel,
                         cudaFuncAttributeMaxDynamicSharedMemorySize, SMEM_BYTES);

    cst3_kernel<<<1, 256>>>(gpv, gpr, param_W, param_b, agg_W1, agg_b1);
    wconv_kernel<<<2560, 512>>>(basis_W2, agg_W1, agg_W2);
    surface_kernel<<<grid, NT, SMEM_BYTES>>>(
        centers, enc_g, enc_node, neighbors, normals, neigh_normals,
        areas, neigh_areas,
        basis_W1, basis_b1, basis_b2, agg_b2, agg_W3, agg_b3, out, n_nodes);
}